// round 5
// baseline (speedup 1.0000x reference)
#include <cuda_runtime.h>

// Problem constants
#define BSZ   4096
#define PSZ   32
#define EMB   128
#define HDIM  768
#define MROWS 16            // batch rows per MLP block

// Scratch: intermediate H [B, 768] (12.6 MB)
__device__ float g_H[BSZ * HDIM];

__device__ __forceinline__ float4 relu_step(float4 x, float4 w, float4 y, float4 bm) {
    float4 r;
    r.x = fmaxf(fmaf(x.x * w.x, y.x, bm.x), 0.f);
    r.y = fmaxf(fmaf(x.y * w.y, y.y, bm.y), 0.f);
    r.z = fmaxf(fmaf(x.z * w.z, y.z, bm.z), 0.f);
    r.w = fmaxf(fmaf(x.w * w.w, y.w, bm.w), 0.f);
    return r;
}

// packed f32x2 FMA: d = a*b + d  (FFMA2 — only reachable via PTX)
__device__ __forceinline__ void fma2(unsigned long long& d,
                                     unsigned long long a,
                                     unsigned long long b) {
    asm("fma.rn.f32x2 %0, %1, %2, %0;" : "+l"(d) : "l"(a), "l"(b));
}

struct PathSmem {
    float sW[3 * EMB];
    float sB[3 * EMB];
    float sAcc[8][256];
    float sCnt[8];
};

template<int L>
__device__ __forceinline__ void path_body(
    PathSmem& sm,
    const int*   __restrict__ ents,
    const int*   __restrict__ mids,
    const float* __restrict__ counts,
    const float* __restrict__ E,
    const float* __restrict__ Wm,
    const float* __restrict__ Bm,
    int gofs)
{
    const int b    = blockIdx.x;
    const int tid  = threadIdx.x;
    const int wid  = tid >> 5;
    const int lane = tid & 31;

    for (int i = tid; i < 3 * EMB; i += 256) { sm.sW[i] = Wm[i]; sm.sB[i] = Bm[i]; }
    __syncthreads();

    int   e[4][L + 1];
    int   m[4][L];
    float cnt[4];
    #pragma unroll
    for (int pp = 0; pp < 4; pp++) {
        const long base = (long)b * PSZ + (wid + pp * 8);
        const int* ep = ents + base * (L + 1);
        const int* mp = mids + base * L;
        #pragma unroll
        for (int i = 0; i <= L; i++) e[pp][i] = ep[i];
        #pragma unroll
        for (int i = 0; i < L; i++)  m[pp][i] = mp[i];
        cnt[pp] = counts[base];
    }

    float4 a1 = make_float4(0.f, 0.f, 0.f, 0.f);
    float4 a2 = make_float4(0.f, 0.f, 0.f, 0.f);
    float  cs = 0.f;

    float4 buf[2][L + 1];
    #pragma unroll
    for (int i = 0; i <= L; i++)
        buf[0][i] = *(const float4*)(E + (long)e[0][i] * EMB + lane * 4);

    #pragma unroll
    for (int pp = 0; pp < 4; pp++) {
        if (pp < 3) {
            #pragma unroll
            for (int i = 0; i <= L; i++)
                buf[(pp + 1) & 1][i] =
                    *(const float4*)(E + (long)e[pp + 1][i] * EMB + lane * 4);
        }
        float4 (&rows)[L + 1] = buf[pp & 1];

        float4 x = rows[0];
        #pragma unroll
        for (int i = 0; i < L; i++) {
            float4 w  = *(const float4*)(sm.sW + m[pp][i] * EMB + lane * 4);
            float4 bb = *(const float4*)(sm.sB + m[pp][i] * EMB + lane * 4);
            x = relu_step(x, w, rows[i + 1], bb);
        }
        const float4 o1 = x;

        const float4 yl = rows[L];
        x = yl;
        #pragma unroll
        for (int i = L - 1; i >= 0; i--) {
            float4 w  = *(const float4*)(sm.sW + m[pp][i] * EMB + lane * 4);
            float4 bb = *(const float4*)(sm.sB + m[pp][i] * EMB + lane * 4);
            x = relu_step(x, w, yl, bb);
        }

        const float c0 = cnt[pp];
        a1.x += c0 * o1.x; a1.y += c0 * o1.y; a1.z += c0 * o1.z; a1.w += c0 * o1.w;
        a2.x += c0 * x.x;  a2.y += c0 * x.y;  a2.z += c0 * x.z;  a2.w += c0 * x.w;
        cs   += c0;
    }

    ((float4*)sm.sAcc[wid])[lane]         = a1;
    ((float4*)(sm.sAcc[wid] + 128))[lane] = a2;
    if (lane == 0) sm.sCnt[wid] = cs;
    __syncthreads();

    float s = 0.f, csum = 0.f;
    #pragma unroll
    for (int w = 0; w < 8; w++) { s += sm.sAcc[w][tid]; csum += sm.sCnt[w]; }
    g_H[(long)b * HDIM + gofs + tid] = s / csum;
}

__global__ __launch_bounds__(256) void paths_kernel(
    const int* __restrict__ ent1, const int* __restrict__ mid1, const float* __restrict__ c1,
    const int* __restrict__ ent2, const int* __restrict__ mid2, const float* __restrict__ c2,
    const int* __restrict__ ent3, const int* __restrict__ mid3, const float* __restrict__ c3,
    const float* __restrict__ E, const float* __restrict__ Wm, const float* __restrict__ Bm)
{
    __shared__ PathSmem sm;
    const int g = blockIdx.y;
    if (g == 0)      path_body<1>(sm, ent1, mid1, c1, E, Wm, Bm, 0);
    else if (g == 1) path_body<2>(sm, ent2, mid2, c2, E, Wm, Bm, 256);
    else             path_body<3>(sm, ent3, mid3, c3, E, Wm, Bm, 512);
}

// ────────────────────────────────────────────────────────────────────────
// MLP head: 16 rows/block, 512 threads, 256 blocks.
// H tile stored TRANSPOSED in smem: sHt[k][16 rows], 16B-granule swizzled
// (granule g at position g ^ (k&3)). Phase A uses packed f32x2 FMA:
// thread = (col c ∈128, K-half kh ∈2, row-group rg ∈2), 8 rows = 4 packed
// accumulator pairs per thread; K halves combined through smem.
// ────────────────────────────────────────────────────────────────────────
__global__ __launch_bounds__(512, 2) void mlp_kernel(
    const float* __restrict__ W1, const float* __restrict__ b1,
    const float* __restrict__ W2, const float* __restrict__ b2,
    const float* __restrict__ W3, const float* __restrict__ b3,
    float* __restrict__ out)
{
    __shared__ float sHt[HDIM * MROWS];   // 48 KB exactly; reused after phase A

    const int b0  = blockIdx.x * MROWS;
    const int tid = threadIdx.x;

    // ── Load + transpose H tile (swizzled) ──────────────────────────────
    {
        const float4* src = (const float4*)(g_H + (long)b0 * HDIM);
        #pragma unroll
        for (int i = 0; i < 6; i++) {
            const int idx = tid + i * 512;        // 0..3071 float4s
            const float4 v = src[idx];
            const int r  = idx / (HDIM / 4);      // row 0..15
            const int kq = idx % (HDIM / 4);      // k-quad
            const int g  = r >> 2, r3 = r & 3;
            const float vv[4] = {v.x, v.y, v.z, v.w};
            #pragma unroll
            for (int j = 0; j < 4; j++) {
                const int k  = kq * 4 + j;
                const int gp = g ^ (k & 3);
                sHt[k * 16 + gp * 4 + r3] = vv[j];
            }
        }
    }
    __syncthreads();

    // ── Phase A: h1 = relu(H @ W1 + b1) with f32x2, K split in halves ───
    const int c  = tid & 127;
    const int kh = (tid >> 7) & 1;
    const int rg = tid >> 8;              // 0: rows 0-7, 1: rows 8-15
    const int gA = rg * 2, gB = rg * 2 + 1;

    unsigned long long a0 = 0ull, a1 = 0ull, a2 = 0ull, a3 = 0ull;

    {
        const float* w1p = W1 + (long)(kh * 384) * 128 + c;
        const int kbase0 = kh * 384;
        #pragma unroll 2
        for (int kk = 0; kk < 384; kk += 4) {
            float w[4];
            #pragma unroll
            for (int j = 0; j < 4; j++) w[j] = __ldg(w1p + (kk + j) * 128);
            #pragma unroll
            for (int j = 0; j < 4; j++) {
                const int k = kbase0 + kk + j;    // k & 3 == j (compile-time)
                unsigned long long w2;
                asm("mov.b64 %0, {%1, %1};" : "=l"(w2) : "f"(w[j]));
                const float* base = sHt + k * 16;
                const ulonglong2 vA = *(const ulonglong2*)(base + ((gA ^ j) << 2));
                const ulonglong2 vB = *(const ulonglong2*)(base + ((gB ^ j) << 2));
                fma2(a0, vA.x, w2);
                fma2(a1, vA.y, w2);
                fma2(a2, vB.x, w2);
                fma2(a3, vB.y, w2);
            }
        }
    }

    // unpack: af[i] = partial for row rg*8 + i
    float af[8];
    {
        const unsigned long long av[4] = {a0, a1, a2, a3};
        #pragma unroll
        for (int i = 0; i < 4; i++) {
            af[2 * i]     = __uint_as_float((unsigned int)av[i]);
            af[2 * i + 1] = __uint_as_float((unsigned int)(av[i] >> 32));
        }
    }
    __syncthreads();                       // all done reading sHt

    float* const scratch = sHt;                    // [8][256] floats (8 KB)
    float* const sh1     = sHt + 2048;             // [16][128]       (8 KB)
    float* const sh2     = sHt + 4096;             // [16][32]        (2 KB)

    const int slot = rg * 128 + c;                 // 0..255
    if (kh == 1) {
        #pragma unroll
        for (int i = 0; i < 8; i++) scratch[i * 256 + slot] = af[i];
    }
    __syncthreads();
    if (kh == 0) {
        const float bias = b1[c];
        #pragma unroll
        for (int i = 0; i < 8; i++) {
            const float v = af[i] + scratch[i * 256 + slot] + bias;
            sh1[(rg * 8 + i) * 128 + c] = fmaxf(v, 0.f);
        }
    }
    __syncthreads();

    // ── Phase B: h2 = relu(h1 @ W2 + b2) — 512 thr = 16 rows × 32 cols ──
    {
        const int r  = tid >> 5;          // warp-uniform → LDS broadcast
        const int c2 = tid & 31;
        float a = b2[c2];
        #pragma unroll 8
        for (int k = 0; k < 128; k += 4) {
            const float4 h = *(const float4*)(sh1 + r * 128 + k);
            a = fmaf(h.x, __ldg(W2 + (k    ) * 32 + c2), a);
            a = fmaf(h.y, __ldg(W2 + (k + 1) * 32 + c2), a);
            a = fmaf(h.z, __ldg(W2 + (k + 2) * 32 + c2), a);
            a = fmaf(h.w, __ldg(W2 + (k + 3) * 32 + c2), a);
        }
        sh2[r * 32 + c2] = fmaxf(a, 0.f);
    }
    __syncthreads();

    // ── Phase C: out = h2 @ W3 + b3 ─────────────────────────────────────
    if (tid < MROWS) {
        float a = b3[0];
        #pragma unroll
        for (int k = 0; k < 32; k++) a = fmaf(sh2[tid * 32 + k], W3[k], a);
        out[b0 + tid] = a;
    }
}

extern "C" void kernel_launch(void* const* d_in, const int* in_sizes, int n_in,
                              void* d_out, int out_size)
{
    const bool dictOrder = (in_sizes[2] == BSZ * PSZ);

    const int *ent1, *mid1, *ent2, *mid2, *ent3, *mid3;
    const float *c1, *c2, *c3;
    if (dictOrder) {
        ent1 = (const int*)d_in[0]; mid1 = (const int*)d_in[1]; c1 = (const float*)d_in[2];
        ent2 = (const int*)d_in[3]; mid2 = (const int*)d_in[4]; c2 = (const float*)d_in[5];
        ent3 = (const int*)d_in[6]; mid3 = (const int*)d_in[7]; c3 = (const float*)d_in[8];
    } else {
        ent1 = (const int*)d_in[0]; mid1 = (const int*)d_in[1];
        ent2 = (const int*)d_in[2]; mid2 = (const int*)d_in[3];
        ent3 = (const int*)d_in[4]; mid3 = (const int*)d_in[5];
        c1 = (const float*)d_in[6]; c2 = (const float*)d_in[7]; c3 = (const float*)d_in[8];
    }
    const float* E  = (const float*)d_in[9];
    const float* Wm = (const float*)d_in[10];
    const float* Bm = (const float*)d_in[11];
    const float* W1 = (const float*)d_in[12];
    const float* b1 = (const float*)d_in[13];
    const float* W2 = (const float*)d_in[14];
    const float* b2 = (const float*)d_in[15];
    const float* W3 = (const float*)d_in[16];
    const float* b3 = (const float*)d_in[17];

    dim3 pgrid(BSZ, 3);
    paths_kernel<<<pgrid, 256>>>(ent1, mid1, c1, ent2, mid2, c2, ent3, mid3, c3,
                                 E, Wm, Bm);
    mlp_kernel<<<BSZ / MROWS, 512>>>(W1, b1, W2, b2, W3, b3, (float*)d_out);
}